// round 3
// baseline (speedup 1.0000x reference)
#include <cuda_runtime.h>
#include <math.h>

// Problem constants
#define TT 16384
#define DD 4096
#define EE 64

// Tiling
#define TM 64            // tokens per CTA
#define KB 32            // k-chunk
#define NC (DD / KB)     // 128 chunks
#define STR 68           // smem row stride (floats), padded: conflict-free f32x4 loads
#define NTHREADS 128

__device__ __forceinline__ unsigned long long pack_dup(float x) {
    unsigned long long r;
    unsigned int u = __float_as_uint(x);
    asm("mov.b64 %0, {%1, %1};" : "=l"(r) : "r"(u));
    return r;
}

__device__ __forceinline__ void ffma2(unsigned long long &d,
                                      unsigned long long a,
                                      unsigned long long b) {
    // packed fp32 FMA (Blackwell f32x2 pipe): d.lo += a.lo*b.lo, d.hi += a.hi*b.hi
    asm("fma.rn.f32x2 %0, %1, %2, %0;" : "+l"(d) : "l"(a), "l"(b));
}

__global__ void __launch_bounds__(NTHREADS, 2)
moe_topk_kernel(const float* __restrict__ A,      // token_hidden [TT, DD]
                const float* __restrict__ R,      // router_logits [TT, EE]
                const float* __restrict__ B,      // expert_ground [EE, DD]
                const float* __restrict__ alphap, // scalar
                float* __restrict__ out)          // [TT, 2, 2]
{
    __shared__ float As[2][KB][STR];   // [buf][k][token]   (transposed)
    __shared__ float Bs[2][KB][STR];   // [buf][k][expert]  (transposed)

    const int tid  = threadIdx.x;
    const int t0   = blockIdx.x * TM;
    const int tg   = tid >> 3;          // token group 0..15 (4 tokens each)
    const int eg   = tid & 7;           // expert group 0..7 (8 experts each)
    const int lrow = tid >> 3;          // staging row 0..15
    const int lk   = (tid & 7) << 2;    // staging k offset 0,4,...,28

    unsigned long long acc[4][4];       // [token][expert-pair], f32x2 packed
#pragma unroll
    for (int i = 0; i < 4; ++i)
#pragma unroll
        for (int j = 0; j < 4; ++j) acc[i][j] = 0ull;

    float4 ra[4], rb[4];
    const float* Abase = A + (size_t)t0 * DD;

    // ---- prologue: load + stage chunk 0 ----
#pragma unroll
    for (int r = 0; r < 4; ++r) {
        ra[r] = *(const float4*)(Abase + (size_t)(lrow + 16 * r) * DD + lk);
        rb[r] = *(const float4*)(B     + (size_t)(lrow + 16 * r) * DD + lk);
    }
#pragma unroll
    for (int r = 0; r < 4; ++r) {
        const int row = lrow + 16 * r;
        As[0][lk + 0][row] = ra[r].x; As[0][lk + 1][row] = ra[r].y;
        As[0][lk + 2][row] = ra[r].z; As[0][lk + 3][row] = ra[r].w;
        Bs[0][lk + 0][row] = rb[r].x; Bs[0][lk + 1][row] = rb[r].y;
        Bs[0][lk + 2][row] = rb[r].z; Bs[0][lk + 3][row] = rb[r].w;
    }
    __syncthreads();

    // ---- main loop: double-buffered ----
    for (int c = 0; c < NC; ++c) {
        const int buf = c & 1;

        if (c + 1 < NC) {
            const int ko = (c + 1) * KB;
#pragma unroll
            for (int r = 0; r < 4; ++r) {
                ra[r] = *(const float4*)(Abase + (size_t)(lrow + 16 * r) * DD + ko + lk);
                rb[r] = *(const float4*)(B     + (size_t)(lrow + 16 * r) * DD + ko + lk);
            }
        }

#pragma unroll
        for (int k = 0; k < KB; ++k) {
            const float4 av = *(const float4*)&As[buf][k][tg * 4];
            const ulonglong2* bp = (const ulonglong2*)&Bs[buf][k][eg * 8];
            const ulonglong2 q0 = bp[0];
            const ulonglong2 q1 = bp[1];
            unsigned long long ap[4];
            ap[0] = pack_dup(av.x); ap[1] = pack_dup(av.y);
            ap[2] = pack_dup(av.z); ap[3] = pack_dup(av.w);
            unsigned long long bv[4];
            bv[0] = q0.x; bv[1] = q0.y; bv[2] = q1.x; bv[3] = q1.y;
#pragma unroll
            for (int i = 0; i < 4; ++i)
#pragma unroll
                for (int j = 0; j < 4; ++j)
                    ffma2(acc[i][j], ap[i], bv[j]);
        }

        if (c + 1 < NC) {
            const int nb = buf ^ 1;
#pragma unroll
            for (int r = 0; r < 4; ++r) {
                const int row = lrow + 16 * r;
                As[nb][lk + 0][row] = ra[r].x; As[nb][lk + 1][row] = ra[r].y;
                As[nb][lk + 2][row] = ra[r].z; As[nb][lk + 3][row] = ra[r].w;
                Bs[nb][lk + 0][row] = rb[r].x; Bs[nb][lk + 1][row] = rb[r].y;
                Bs[nb][lk + 2][row] = rb[r].z; Bs[nb][lk + 3][row] = rb[r].w;
            }
            __syncthreads();
        }
    }

    // ---- epilogue: dump C tile to smem (reuse As: 2*32*68 = 4352 floats = 64*68) ----
    __syncthreads();
    float* Cs = &As[0][0][0];
#pragma unroll
    for (int i = 0; i < 4; ++i) {
        const int tok = tg * 4 + i;
#pragma unroll
        for (int j = 0; j < 4; ++j) {
            const float lo = __uint_as_float((unsigned int)(acc[i][j] & 0xffffffffull));
            const float hi = __uint_as_float((unsigned int)(acc[i][j] >> 32));
            Cs[tok * STR + eg * 8 + 2 * j + 0] = lo;
            Cs[tok * STR + eg * 8 + 2 * j + 1] = hi;
        }
    }
    __syncthreads();

    // ---- per-token top-2 + softmax ----
    if (tid < TM) {
        const int t = t0 + tid;
        const float alpha = *alphap;
        const float4* rr = (const float4*)(R + (size_t)t * EE);
        const float4* cc = (const float4*)(Cs + tid * STR);

        float m1 = -3.0e38f, m2 = -3.0e38f;
        int i1 = 0, i2 = 0;
#pragma unroll
        for (int e4 = 0; e4 < EE / 4; ++e4) {
            const float4 rv = rr[e4];
            const float4 cv = cc[e4];
            float g[4];
            g[0] = rv.x + alpha * cv.x;
            g[1] = rv.y + alpha * cv.y;
            g[2] = rv.z + alpha * cv.z;
            g[3] = rv.w + alpha * cv.w;
#pragma unroll
            for (int u = 0; u < 4; ++u) {
                const int e = e4 * 4 + u;
                if (g[u] > m1) { m2 = m1; i2 = i1; m1 = g[u]; i1 = e; }
                else if (g[u] > m2) { m2 = g[u]; i2 = e; }
            }
        }
        const float ed = expf(m2 - m1);      // <= 1
        const float inv = 1.0f / (1.0f + ed);
        const float w1 = inv;
        const float w2 = ed * inv;
        *(float4*)(out + 4 * (size_t)t) =
            make_float4((float)i1, w1, (float)i2, w2);
    }
}

extern "C" void kernel_launch(void* const* d_in, const int* in_sizes, int n_in,
                              void* d_out, int out_size) {
    const float* A     = (const float*)d_in[0];  // token_hidden [16384, 4096]
    const float* R     = (const float*)d_in[1];  // router_logits [16384, 64]
    const float* B     = (const float*)d_in[2];  // expert_ground [64, 4096]
    const float* alpha = (const float*)d_in[3];  // scalar
    float* out = (float*)d_out;                  // [16384, 2, 2]

    dim3 grid(TT / TM);       // 256 CTAs
    dim3 block(NTHREADS);     // 128 threads
    moe_topk_kernel<<<grid, block>>>(A, R, B, alpha, out);
}

// round 9
// speedup vs baseline: 3.1898x; 3.1898x over previous
#include <cuda_runtime.h>
#include <math.h>

#define TT 16384
#define DD 4096
#define EE 64
#define SPLIT 4
#define KSEG (DD / SPLIT)     // 1024
#define TM 64                 // tokens per CTA
#define KB 32                 // k-chunk
#define NCC (KSEG / KB)       // 32 chunks per CTA
#define ASTR 36               // A smem row stride (floats): 144B, 16B-aligned, 2-way max
#define BSTR 68               // B smem row stride (floats): 64 + 4 skew room
#define NTH 128

__device__ float g_Bt[DD * EE];          // 1 MB: B transposed [k][e]
__device__ float g_part[SPLIT * TT * EE];// 16 MB: split-K partials

__device__ __forceinline__ unsigned long long pack_dup(float x) {
    unsigned long long r; unsigned int u = __float_as_uint(x);
    asm("mov.b64 %0, {%1, %1};" : "=l"(r) : "r"(u));
    return r;
}
__device__ __forceinline__ void ffma2(unsigned long long &d,
                                      unsigned long long a,
                                      unsigned long long b) {
    asm("fma.rn.f32x2 %0, %1, %2, %0;" : "+l"(d) : "l"(a), "l"(b));
}
__device__ __forceinline__ void cp16(unsigned dst, const void* src) {
    asm volatile("cp.async.ca.shared.global [%0], [%1], 16;" :: "r"(dst), "l"(src));
}
__device__ __forceinline__ float sel4(const float4 v, int kk) {
    return kk == 0 ? v.x : kk == 1 ? v.y : kk == 2 ? v.z : v.w;  // kk compile-time
}

// ---------- kernel 1: transpose B[64][4096] -> g_Bt[4096][64] ----------
__global__ void bt_kernel(const float* __restrict__ B) {
    __shared__ float tile[64][65];
    const int k0 = blockIdx.x * 64;
    const int tid = threadIdx.x;
    for (int idx = tid; idx < 64 * 64; idx += 256) {
        const int e = idx >> 6, k = idx & 63;
        tile[e][k] = B[(size_t)e * DD + k0 + k];
    }
    __syncthreads();
    for (int idx = tid; idx < 64 * 64; idx += 256) {
        const int k = idx >> 6, e = idx & 63;
        g_Bt[(size_t)(k0 + k) * EE + e] = tile[e][k];
    }
}

// ---------- kernel 2: split-K GEMM -> g_part ----------
__device__ __forceinline__ void stage_chunk(unsigned as_u, unsigned bs_u,
                                            const float* Abase, const float* Btbase,
                                            int c, int tid) {
    // A: 64 tok x 32 k = 512 x 16B, natural [tok][k] layout, fully coalesced
#pragma unroll
    for (int r = 0; r < 4; ++r) {
        const int idx = r * NTH + tid;
        const int tok = idx >> 3, kq = (idx & 7) << 2;
        cp16(as_u + (unsigned)(tok * ASTR + kq) * 4u,
             Abase + (size_t)tok * DD + c * KB + kq);
    }
    // B: 32 k x 64 e = 512 x 16B, skewed (+4 floats for e>=32), coalesced
#pragma unroll
    for (int r = 0; r < 4; ++r) {
        const int idx = r * NTH + tid;
        const int k = idx >> 4, e4 = idx & 15;
        const int col = (e4 << 2) + ((e4 >> 3) << 2);
        cp16(bs_u + (unsigned)(k * BSTR + col) * 4u,
             Btbase + (size_t)(c * KB + k) * EE + (e4 << 2));
    }
    asm volatile("cp.async.commit_group;");
}

__global__ void __launch_bounds__(NTH, 4)
gemm_kernel(const float* __restrict__ A) {
    __shared__ float As[2][TM][ASTR];   // [buf][token][k]
    __shared__ float Bs[2][KB][BSTR];   // [buf][k][expert(skewed)]

    const int tid = threadIdx.x;
    const int t0  = blockIdx.x * TM;
    const int kbase = blockIdx.y * KSEG;
    const int tg  = tid >> 3;                      // token group 0..15
    const int eg  = tid & 7;                       // expert group 0..7
    const int bcol = eg * 8 + (eg >> 2) * 4;       // skewed expert column

    unsigned long long acc[4][4];
#pragma unroll
    for (int i = 0; i < 4; ++i)
#pragma unroll
        for (int j = 0; j < 4; ++j) acc[i][j] = 0ull;

    const float* Abase  = A + (size_t)t0 * DD + kbase;
    const float* Btbase = g_Bt + (size_t)kbase * EE;

    const unsigned as0 = (unsigned)__cvta_generic_to_shared(&As[0][0][0]);
    const unsigned bs0 = (unsigned)__cvta_generic_to_shared(&Bs[0][0][0]);
    const unsigned asz = TM * ASTR * 4u;
    const unsigned bsz = KB * BSTR * 4u;

    stage_chunk(as0, bs0, Abase, Btbase, 0, tid);

    for (int c = 0; c < NCC; ++c) {
        const int buf = c & 1;
        if (c + 1 < NCC) {
            stage_chunk(as0 + (buf ^ 1) * asz, bs0 + (buf ^ 1) * bsz,
                        Abase, Btbase, c + 1, tid);
            asm volatile("cp.async.wait_group 1;");
        } else {
            asm volatile("cp.async.wait_group 0;");
        }
        __syncthreads();

#pragma unroll
        for (int kg = 0; kg < KB / 4; ++kg) {
            const float4 a0 = *(const float4*)&As[buf][tg * 4 + 0][kg * 4];
            const float4 a1 = *(const float4*)&As[buf][tg * 4 + 1][kg * 4];
            const float4 a2 = *(const float4*)&As[buf][tg * 4 + 2][kg * 4];
            const float4 a3 = *(const float4*)&As[buf][tg * 4 + 3][kg * 4];
#pragma unroll
            for (int kk = 0; kk < 4; ++kk) {
                const int k = kg * 4 + kk;
                const ulonglong2 q0 = *(const ulonglong2*)&Bs[buf][k][bcol];
                const ulonglong2 q1 = *(const ulonglong2*)&Bs[buf][k][bcol + 4];
                const unsigned long long p0 = pack_dup(sel4(a0, kk));
                const unsigned long long p1 = pack_dup(sel4(a1, kk));
                const unsigned long long p2 = pack_dup(sel4(a2, kk));
                const unsigned long long p3 = pack_dup(sel4(a3, kk));
                ffma2(acc[0][0], p0, q0.x); ffma2(acc[0][1], p0, q0.y);
                ffma2(acc[0][2], p0, q1.x); ffma2(acc[0][3], p0, q1.y);
                ffma2(acc[1][0], p1, q0.x); ffma2(acc[1][1], p1, q0.y);
                ffma2(acc[1][2], p1, q1.x); ffma2(acc[1][3], p1, q1.y);
                ffma2(acc[2][0], p2, q0.x); ffma2(acc[2][1], p2, q0.y);
                ffma2(acc[2][2], p2, q1.x); ffma2(acc[2][3], p2, q1.y);
                ffma2(acc[3][0], p3, q0.x); ffma2(acc[3][1], p3, q0.y);
                ffma2(acc[3][2], p3, q1.x); ffma2(acc[3][3], p3, q1.y);
            }
        }
        __syncthreads();   // all reads of buf done before it is re-staged
    }

    // write partials: packed u64 pairs are consecutive experts -> direct STG.128
    float* outp = g_part + ((size_t)blockIdx.y * TT + t0) * EE;
#pragma unroll
    for (int i = 0; i < 4; ++i) {
        float* dst = outp + (size_t)(tg * 4 + i) * EE + eg * 8;
        *(ulonglong2*)(dst)     = make_ulonglong2(acc[i][0], acc[i][1]);
        *(ulonglong2*)(dst + 4) = make_ulonglong2(acc[i][2], acc[i][3]);
    }
}

// ---------- kernel 3: reduce splits + top-2 + softmax ----------
__global__ void __launch_bounds__(256)
reduce_topk_kernel(const float* __restrict__ R, const float* __restrict__ alphap,
                   float* __restrict__ out) {
    const int t = blockIdx.x * 256 + threadIdx.x;
    const float alpha = *alphap;
    const float4* rr = (const float4*)(R + (size_t)t * EE);
    const float4* pp = (const float4*)(g_part + (size_t)t * EE);
    const size_t ss = (size_t)TT * EE / 4;   // split stride in float4

    float m1 = -3.0e38f, m2 = -3.0e38f;
    int i1 = 0, i2 = 0;
#pragma unroll
    for (int e4 = 0; e4 < EE / 4; ++e4) {
        const float4 rv = rr[e4];
        const float4 s0 = pp[e4];
        const float4 s1 = pp[ss + e4];
        const float4 s2 = pp[2 * ss + e4];
        const float4 s3 = pp[3 * ss + e4];
        float g[4];
        g[0] = rv.x + alpha * ((s0.x + s1.x) + (s2.x + s3.x));
        g[1] = rv.y + alpha * ((s0.y + s1.y) + (s2.y + s3.y));
        g[2] = rv.z + alpha * ((s0.z + s1.z) + (s2.z + s3.z));
        g[3] = rv.w + alpha * ((s0.w + s1.w) + (s2.w + s3.w));
#pragma unroll
        for (int u = 0; u < 4; ++u) {
            const int e = e4 * 4 + u;
            if (g[u] > m1) { m2 = m1; i2 = i1; m1 = g[u]; i1 = e; }
            else if (g[u] > m2) { m2 = g[u]; i2 = e; }
        }
    }
    const float ed  = expf(m2 - m1);
    const float inv = 1.0f / (1.0f + ed);
    *(float4*)(out + 4 * (size_t)t) =
        make_float4((float)i1, inv, (float)i2, ed * inv);
}

extern "C" void kernel_launch(void* const* d_in, const int* in_sizes, int n_in,
                              void* d_out, int out_size) {
    const float* A     = (const float*)d_in[0];  // token_hidden [16384, 4096]
    const float* R     = (const float*)d_in[1];  // router_logits [16384, 64]
    const float* B     = (const float*)d_in[2];  // expert_ground [64, 4096]
    const float* alpha = (const float*)d_in[3];  // scalar
    float* out = (float*)d_out;                  // [16384, 2, 2]

    bt_kernel<<<DD / 64, 256>>>(B);
    gemm_kernel<<<dim3(TT / TM, SPLIT), NTH>>>(A);
    reduce_topk_kernel<<<TT / 256, 256>>>(R, alpha, out);
}